// round 7
// baseline (speedup 1.0000x reference)
#include <cuda_runtime.h>

#define N 8192
#define D 256
#define NC 10
#define GRID 512
#define BLOCK 256
#define RPB (N / GRID)       // 16 rows per block
#define NSUB 4               // row sub-groups (replicas)
#define CPT (RPB / NSUB)     // 4 rows per thread

// PAR = COV * 0.5 / BATCH_SIZE = 0.5 / 8192
#define PARF 6.103515625e-05

// Global accumulators. Statically zero-initialized; the finishing block
// resets them after consuming, so every launch / graph replay sees zeros.
__device__ float4 g_v4[NC][D / 4];   // per-class column sums, viewed as float[NC][D]
__device__ float  g_S[NC];           // per-class scalar sum of squares
__device__ int    g_cnt[NC];
__device__ unsigned int g_done;

__device__ __forceinline__ void red_add_v4(float4* addr, float4 v) {
    asm volatile("red.global.add.v4.f32 [%0], {%1, %2, %3, %4};"
                 :: "l"(addr), "f"(v.x), "f"(v.y), "f"(v.z), "f"(v.w)
                 : "memory");
}

__global__ __launch_bounds__(BLOCK) void fused_kernel(const float* __restrict__ out,
                                                      const int* __restrict__ label,
                                                      float* __restrict__ res) {
    __shared__ float  sv[NSUB][NC][D];   // 40 KB: per-replica per-class column sums
    __shared__ float  sS[NC];            // per-class sum of squares (block partial)
    __shared__ int    s_lab[RPB];
    __shared__ int    scnt[NC];
    __shared__ int    s_last;
    __shared__ double red[BLOCK];        // 2 KB
    __shared__ double red2[BLOCK];       // 2 KB
    __shared__ double s_xx0, s_xxL;

    int t   = threadIdx.x;
    int cg  = t & 63;      // column group: owns cols 4*cg .. 4*cg+3
    int sub = t >> 6;      // row sub-group 0..3 (doubles as replica index)
    int r0  = blockIdx.x * RPB;

    #pragma unroll
    for (int c = 0; c < NC; c++)
        *(float4*)&sv[sub][c][4 * cg] = make_float4(0.f, 0.f, 0.f, 0.f);
    if (t < NC) { sS[t] = 0.f; scnt[t] = 0; }
    if (t < RPB) s_lab[t] = label[r0 + t];
    __syncthreads();

    if (t < RPB) atomicAdd(&scnt[s_lab[t]], 1);

    // ---- accumulate: 4 rows per thread, 4 columns each (float4) ----
    const float4* src = (const float4*)out;   // row stride D/4 = 64 float4s
    #pragma unroll
    for (int i = 0; i < CPT; i++) {
        int r = r0 + sub * CPT + i;
        float4 x = src[(size_t)r * (D / 4) + cg];
        int l = s_lab[sub * CPT + i];          // warp-uniform (whole warp = same row)

        float4* slot = (float4*)&sv[sub][l][4 * cg];
        float4 a = *slot;
        a.x += x.x; a.y += x.y; a.z += x.z; a.w += x.w;
        *slot = a;

        // per-class scalar sum of squares: warp shuffle-reduce, one ATOMS/warp
        float ss = x.x * x.x + x.y * x.y + x.z * x.z + x.w * x.w;
        #pragma unroll
        for (int o = 16; o; o >>= 1) ss += __shfl_xor_sync(0xffffffffu, ss, o);
        if ((t & 31) == 0) atomicAdd(&sS[l], ss);
    }
    __syncthreads();

    // ---- flush block partials: 64 threads x 10 vector REDs ----
    if (t < 64) {
        #pragma unroll
        for (int c = 0; c < NC; c++) {
            float4 a = *(float4*)&sv[0][c][4 * t];
            float4 b = *(float4*)&sv[1][c][4 * t];
            float4 d = *(float4*)&sv[2][c][4 * t];
            float4 e = *(float4*)&sv[3][c][4 * t];
            red_add_v4(&g_v4[c][t],
                       make_float4(a.x + b.x + d.x + e.x,
                                   a.y + b.y + d.y + e.y,
                                   a.z + b.z + d.z + e.z,
                                   a.w + b.w + d.w + e.w));
        }
    }
    if (t < NC) {
        if (scnt[t]) atomicAdd(&g_cnt[t], scnt[t]);
        atomicAdd(&g_S[t], sS[t]);
    }

    // ---- last-block-arrival handoff ----
    __threadfence();
    __syncthreads();
    if (t == 0) s_last = (atomicAdd(&g_done, 1u) == GRID - 1);
    __syncthreads();
    if (!s_last) return;

    // =================== finish phase (one block) ===================
    __threadfence();   // acquire side of the counter handshake

    __shared__ int   cnt[NC];
    __shared__ float Sc[NC];
    if (t < NC) { cnt[t] = g_cnt[t]; g_cnt[t] = 0;
                  Sc[t]  = g_S[t];   g_S[t]  = 0.f; }
    if (t == 0) g_done = 0;

    int l0 = label[0];
    int lL = label[N - 1];
    // Row set A = [0, N-1) excludes row N-1; B = [1, N) excludes row 0.
    float x0 = out[t];                        // row 0,   column t
    float xL = out[(size_t)(N - 1) * D + t];  // row N-1, column t

    // ||x0||^2 and ||xL||^2 (needed for the scalar edge corrections)
    red[t]  = (double)x0 * (double)x0;
    red2[t] = (double)xL * (double)xL;
    __syncthreads();
    #pragma unroll
    for (int s = BLOCK / 2; s > 0; s >>= 1) {
        if (t < s) { red[t] += red[t + s]; red2[t] += red2[t + s]; }
        __syncthreads();
    }
    if (t == 0) { s_xx0 = red[0]; s_xxL = red2[0]; }
    __syncthreads();

    // Per-column contributions:  -4 * sum_c vA_c[t]*vB_c[t]  +  2 * uA[t]*uB[t]
    float* gv = (float*)g_v4;     // [NC][D]
    double p = 0.0;
    float uAt = 0.f, uBt = 0.f;
    #pragma unroll
    for (int c = 0; c < NC; c++) {
        float v = gv[c * D + t];
        gv[c * D + t] = 0.f;       // consume + reset (sole reader of this word)
        float vA = v - ((lL == c) ? xL : 0.f);
        float vB = v - ((l0 == c) ? x0 : 0.f);
        p -= 4.0 * (double)vA * (double)vB;
        uAt += vA; uBt += vB;
    }
    p += 2.0 * (double)uAt * (double)uBt;

    // Scalar part: 2*sum_c [nB*SA_c + nA*SB_c]  -  (N-1)*(SA + SB)
    if (t == 0) {
        double sc = 0.0, SA = 0.0, SB = 0.0;
        #pragma unroll
        for (int c = 0; c < NC; c++) {
            double S  = (double)Sc[c];
            double SAc = S - ((lL == c) ? s_xxL : 0.0);
            double SBc = S - ((l0 == c) ? s_xx0 : 0.0);
            double nA = (double)(cnt[c] - (lL == c));
            double nB = (double)(cnt[c] - (l0 == c));
            sc += 2.0 * (nB * SAc + nA * SBc);
            SA += SAc; SB += SBc;
        }
        sc -= (double)(N - 1) * (SA + SB);
        p += sc;
    }

    red[t] = p;
    __syncthreads();
    #pragma unroll
    for (int s = BLOCK / 2; s > 0; s >>= 1) {
        if (t < s) red[t] += red[t + s];
        __syncthreads();
    }
    if (t == 0) res[0] = (float)(PARF * red[0]);
}

extern "C" void kernel_launch(void* const* d_in, const int* in_sizes, int n_in,
                              void* d_out, int out_size) {
    const float* out   = (const float*)d_in[0];
    const int*   label = (const int*)d_in[1];
    fused_kernel<<<GRID, BLOCK>>>(out, label, (float*)d_out);
}

// round 8
// speedup vs baseline: 1.0523x; 1.0523x over previous
#include <cuda_runtime.h>

#define N 8192
#define D 256
#define NC 10
#define GRID 128
#define BLOCK 256
#define RPB (N / GRID)       // 64 rows per block
#define NSUB 4               // row sub-groups
#define RPT (RPB / NSUB)     // 16 rows per thread

// PAR = COV * 0.5 / BATCH_SIZE = 0.5 / 8192
#define PARF 6.103515625e-05

// Global accumulators. Statically zero-initialized; the finishing block
// resets them after consuming, so every launch / graph replay sees zeros.
__device__ float4 g_v4[NC][D / 4];   // per-class column sums (float[NC][D])
__device__ float  g_S[NC];           // per-class scalar sum of squares
__device__ int    g_cnt[NC];
__device__ unsigned int g_done;

__device__ __forceinline__ void red_add_v4(float4* addr, float4 v) {
    asm volatile("red.global.add.v4.f32 [%0], {%1, %2, %3, %4};"
                 :: "l"(addr), "f"(v.x), "f"(v.y), "f"(v.z), "f"(v.w)
                 : "memory");
}

__global__ __launch_bounds__(BLOCK) void fused_kernel(const float* __restrict__ out,
                                                      const int* __restrict__ label,
                                                      float* __restrict__ res) {
    __shared__ float  stage[NSUB][NC][D];   // 40 KB: flush staging ONLY (not in mainloop)
    __shared__ float  sS[NC];
    __shared__ int    s_lab[RPB];
    __shared__ int    scnt[NC];
    __shared__ int    s_last;
    __shared__ double red[BLOCK];
    __shared__ double red2[BLOCK];
    __shared__ double s_xx0, s_xxL;

    int t   = threadIdx.x;
    int cg  = t & 63;      // column group: owns cols 4*cg .. 4*cg+3
    int sub = t >> 6;      // row sub-group 0..3 (warp-uniform)
    int r0  = blockIdx.x * RPB;

    if (t < NC) { sS[t] = 0.f; scnt[t] = 0; }
    if (t < RPB) s_lab[t] = label[r0 + t];
    __syncthreads();

    if (t < RPB) atomicAdd(&scnt[s_lab[t]], 1);

    // ---- mainloop: register-resident per-class accumulation, zero smem RMW ----
    float4 acc[NC];
    float  ssc[NC];
    #pragma unroll
    for (int c = 0; c < NC; c++) { acc[c] = make_float4(0.f, 0.f, 0.f, 0.f); ssc[c] = 0.f; }

    const float4* src = (const float4*)out;   // row stride D/4 = 64
    int rbase = r0 + sub * RPT;
    #pragma unroll 4
    for (int i = 0; i < RPT; i++) {
        float4 x = src[(size_t)(rbase + i) * (D / 4) + cg];
        int l = s_lab[sub * RPT + i];          // warp-uniform
        float dot = x.x * x.x + x.y * x.y + x.z * x.z + x.w * x.w;
        #pragma unroll
        for (int c = 0; c < NC; c++) {
            if (l == c) {                       // predicated; independent across c
                acc[c].x += x.x; acc[c].y += x.y;
                acc[c].z += x.z; acc[c].w += x.w;
                ssc[c] += dot;
            }
        }
    }

    // ---- per-class sum-of-squares: warp shuffle-reduce, lane0 -> smem ----
    #pragma unroll
    for (int c = 0; c < NC; c++) {
        float s = ssc[c];
        #pragma unroll
        for (int o = 16; o; o >>= 1) s += __shfl_xor_sync(0xffffffffu, s, o);
        if ((t & 31) == 0 && s != 0.f) atomicAdd(&sS[c], s);
    }

    // ---- stage register accs to smem, combine sub-groups, flush REDs ----
    #pragma unroll
    for (int c = 0; c < NC; c++)
        *(float4*)&stage[sub][c][4 * cg] = acc[c];
    __syncthreads();

    if (t < 64) {
        #pragma unroll
        for (int c = 0; c < NC; c++) {
            float4 a = *(float4*)&stage[0][c][4 * t];
            float4 b = *(float4*)&stage[1][c][4 * t];
            float4 d = *(float4*)&stage[2][c][4 * t];
            float4 e = *(float4*)&stage[3][c][4 * t];
            red_add_v4(&g_v4[c][t],
                       make_float4(a.x + b.x + d.x + e.x,
                                   a.y + b.y + d.y + e.y,
                                   a.z + b.z + d.z + e.z,
                                   a.w + b.w + d.w + e.w));
        }
    }
    if (t < NC) {
        if (scnt[t]) atomicAdd(&g_cnt[t], scnt[t]);
        atomicAdd(&g_S[t], sS[t]);
    }

    // ---- last-block-arrival handoff ----
    __threadfence();
    __syncthreads();
    if (t == 0) s_last = (atomicAdd(&g_done, 1u) == GRID - 1);
    __syncthreads();
    if (!s_last) return;

    // =================== finish phase (one block) ===================
    __threadfence();   // acquire side of the counter handshake

    __shared__ int   cnt[NC];
    __shared__ float Sc[NC];
    if (t < NC) { cnt[t] = g_cnt[t]; g_cnt[t] = 0;
                  Sc[t]  = g_S[t];   g_S[t]  = 0.f; }
    if (t == 0) g_done = 0;

    int l0 = label[0];
    int lL = label[N - 1];
    // Row set A = [0, N-1) excludes row N-1; B = [1, N) excludes row 0.
    float x0 = out[t];                        // row 0,   column t
    float xL = out[(size_t)(N - 1) * D + t];  // row N-1, column t

    // ||x0||^2 and ||xL||^2 (scalar edge corrections)
    red[t]  = (double)x0 * (double)x0;
    red2[t] = (double)xL * (double)xL;
    __syncthreads();
    #pragma unroll
    for (int s = BLOCK / 2; s > 0; s >>= 1) {
        if (t < s) { red[t] += red[t + s]; red2[t] += red2[t + s]; }
        __syncthreads();
    }
    if (t == 0) { s_xx0 = red[0]; s_xxL = red2[0]; }
    __syncthreads();

    // Per-column:  -4 * sum_c vA_c[t]*vB_c[t]  +  2 * uA[t]*uB[t]
    float* gv = (float*)g_v4;     // [NC][D]
    double p = 0.0;
    float uAt = 0.f, uBt = 0.f;
    #pragma unroll
    for (int c = 0; c < NC; c++) {
        float v = gv[c * D + t];
        gv[c * D + t] = 0.f;       // consume + reset
        float vA = v - ((lL == c) ? xL : 0.f);
        float vB = v - ((l0 == c) ? x0 : 0.f);
        p -= 4.0 * (double)vA * (double)vB;
        uAt += vA; uBt += vB;
    }
    p += 2.0 * (double)uAt * (double)uBt;

    // Scalar part: 2*sum_c [nB*SA_c + nA*SB_c]  -  (N-1)*(SA + SB)
    if (t == 0) {
        double sc = 0.0, SA = 0.0, SB = 0.0;
        #pragma unroll
        for (int c = 0; c < NC; c++) {
            double S   = (double)Sc[c];
            double SAc = S - ((lL == c) ? s_xxL : 0.0);
            double SBc = S - ((l0 == c) ? s_xx0 : 0.0);
            double nA  = (double)(cnt[c] - (lL == c));
            double nB  = (double)(cnt[c] - (l0 == c));
            sc += 2.0 * (nB * SAc + nA * SBc);
            SA += SAc; SB += SBc;
        }
        sc -= (double)(N - 1) * (SA + SB);
        p += sc;
    }

    red[t] = p;
    __syncthreads();
    #pragma unroll
    for (int s = BLOCK / 2; s > 0; s >>= 1) {
        if (t < s) red[t] += red[t + s];
        __syncthreads();
    }
    if (t == 0) res[0] = (float)(PARF * red[0]);
}

extern "C" void kernel_launch(void* const* d_in, const int* in_sizes, int n_in,
                              void* d_out, int out_size) {
    const float* out   = (const float*)d_in[0];
    const int*   label = (const int*)d_in[1];
    fused_kernel<<<GRID, BLOCK>>>(out, label, (float*)d_out);
}